// round 16
// baseline (speedup 1.0000x reference)
#include <cuda_runtime.h>
#include <cuda_fp16.h>
#include <cstdint>

#define D 96
#define MAX_N 50000
#define MAXDEG 64
#define MAX_OVF 4096

// ---- scratch (static device globals; no allocation) -----------------------
__device__ __align__(16) uint16_t g_ah[MAX_N * D];   // fp16 aggr + x
__device__ __align__(16) uint16_t g_wh[D * D];       // fp16 W
__device__ int      g_cnt[MAX_N];               // per-node cursor / degree
__device__ int2     g_pack[MAX_N * MAXDEG];     // (src, bitcast(w)) buckets
__device__ int      g_ovfcnt;
__device__ int4     g_ovf[MAX_OVF];             // (src, dst, bitcast(w), pad)
__device__ int      g_done;                     // warp ticket for state reset

__device__ __forceinline__ uint32_t smem_u32(const void* p) {
    uint32_t a;
    asm("{ .reg .u64 t; cvta.to.shared.u64 t, %1; cvt.u32.u64 %0, t; }"
        : "=r"(a) : "l"(p));
    return a;
}

// ---------------------------------------------------------------------------
// K0: convert W to fp16 (tiny: 36 blocks).
// ---------------------------------------------------------------------------
__global__ void wconv_kernel(const float* __restrict__ Wm) {
    int i = blockIdx.x * blockDim.x + threadIdx.x;
    if (i < D * D)
        g_wh[i] = __half_as_ushort(__float2half_rn(__ldg(Wm + i)));
}

// ---------------------------------------------------------------------------
// K1: bucket edges. EPT=4, 16 regs, high occupancy (atomic-latency bound).
// g_cnt is zero on entry (module-load zero-init; self-cleaned by aggregate).
// ---------------------------------------------------------------------------
#define EPT 4
__global__ void bucket_kernel(const int* __restrict__ ei,
                              const float* __restrict__ ew,
                              const float* __restrict__ pr,
                              int E) {
    int base = (blockIdx.x * blockDim.x + threadIdx.x) * EPT;
    int src[EPT], dst[EPT];
    float w[EPT];
#pragma unroll
    for (int u = 0; u < EPT; u++) {
        int e = base + u;
        if (e < E) { src[u] = __ldg(ei + e); dst[u] = __ldg(ei + E + e); w[u] = __ldg(ew + e); }
    }
#pragma unroll
    for (int u = 0; u < EPT; u++) {
        int e = base + u;
        if (e < E) w[u] *= __ldg(pr + src[u]);
    }
#pragma unroll
    for (int u = 0; u < EPT; u++) {
        int e = base + u;
        if (e < E) {
            int pos = atomicAdd(&g_cnt[dst[u]], 1);
            if (pos < MAXDEG) {
                g_pack[dst[u] * MAXDEG + pos] = make_int2(src[u], __float_as_int(w[u]));
            } else {
                int o = atomicAdd(&g_ovfcnt, 1);
                if (o < MAX_OVF)
                    g_ovf[o] = make_int4(src[u], dst[u], __float_as_int(w[u]), 0);
            }
        }
    }
}

// ---------------------------------------------------------------------------
// K2: per-node aggregation. One warp per node; residual +x folded; fp32
// accumulate; OUTPUT fp16 (coalesced 64B half-stores). Self-cleans g_cnt;
// per-warp ticket resets g_ovfcnt/g_done after every warp's ovf read.
// ---------------------------------------------------------------------------
__global__ void aggregate_kernel(const float* __restrict__ x, int N,
                                 int total_warps) {
    __shared__ int2 s_pack[8][MAXDEG];

    int wid  = threadIdx.x >> 5;
    int l    = threadIdx.x & 31;
    int node = blockIdx.x * 8 + wid;

    int ovf = g_ovfcnt;
    if (ovf > MAX_OVF) ovf = MAX_OVF;

    if (node < N) {
        int cnt = g_cnt[node];
        if (cnt > MAXDEG) cnt = MAXDEG;

        const int2* bucket = g_pack + (size_t)node * MAXDEG;
        for (int k = l; k < cnt; k += 32)
            s_pack[wid][k] = __ldg(bucket + k);
        __syncwarp();

        const float* xr0 = x + (size_t)node * D;
        float a0 = __ldg(xr0 + l);
        float a1 = __ldg(xr0 + 32 + l);
        float a2 = __ldg(xr0 + 64 + l);

        int j = 0;
        for (; j + 4 <= cnt; j += 4) {
            int   s[4]; float w[4];
#pragma unroll
            for (int u = 0; u < 4; u++) {
                int2 p = s_pack[wid][j + u];
                s[u] = p.x; w[u] = __int_as_float(p.y);
            }
            float b0[4], b1[4], b2[4];
#pragma unroll
            for (int u = 0; u < 4; u++) {
                const float* xr = x + (size_t)s[u] * D;
                b0[u] = __ldg(xr + l);
                b1[u] = __ldg(xr + 32 + l);
                b2[u] = __ldg(xr + 64 + l);
            }
#pragma unroll
            for (int u = 0; u < 4; u++) {
                a0 += w[u] * b0[u];
                a1 += w[u] * b1[u];
                a2 += w[u] * b2[u];
            }
        }
        for (; j < cnt; j++) {
            int2 p = s_pack[wid][j];
            float w = __int_as_float(p.y);
            const float* xr = x + (size_t)p.x * D;
            a0 += w * __ldg(xr + l);
            a1 += w * __ldg(xr + 32 + l);
            a2 += w * __ldg(xr + 64 + l);
        }

        if (ovf > 0) {
            for (int i = 0; i < ovf; i++) {
                int4 p = g_ovf[i];
                if (p.y == node) {
                    float w = __int_as_float(p.z);
                    const float* xr = x + (size_t)p.x * D;
                    a0 += w * __ldg(xr + l);
                    a1 += w * __ldg(xr + 32 + l);
                    a2 += w * __ldg(xr + 64 + l);
                }
            }
        }

        uint16_t* o = g_ah + (size_t)node * D;
        o[l]      = __half_as_ushort(__float2half_rn(a0));
        o[32 + l] = __half_as_ushort(__float2half_rn(a1));
        o[64 + l] = __half_as_ushort(__float2half_rn(a2));
    }

    // self-clean + per-warp ticket (this warp's g_ovf read is done)
    if (l == 0) {
        if (node < N) g_cnt[node] = 0;
        __threadfence();
        if (atomicAdd(&g_done, 1) == total_warps - 1) {
            g_ovfcnt = 0;
            g_done = 0;
        }
    }
}

// ---------------------------------------------------------------------------
// K3: fp16 mma.sync GEMM (m16n8k16) — grid-strided, double-buffered.
// Each CTA loads W once, loops 64-node tiles; prefetch next A while computing.
// 8 warps = 2 M-groups (32 rows) x 4 N-groups (24 cols); warp tile 2m16 x 3n8;
// 6 K-steps of 16. smem row pitch 104 halves = 52 words (52 % 32 = 20 ->
// all fragment LDS conflict-free). smem = 20 + 2x13.3 = 46.6KB -> 3 CTAs/SM.
// ---------------------------------------------------------------------------
#define SW2 52        // 32-bit words per smem row (104 halves)
#define NTILE 64
__global__ __launch_bounds__(256, 3)
void gemm_h_kernel(const float* __restrict__ bias,
                   float* __restrict__ out,
                   int N, int ntiles) {
    extern __shared__ uint32_t smem[];
    uint32_t* sW  = smem;                    // [96][SW2]
    uint32_t* sA0 = smem + D * SW2;          // [64][SW2] buffer 0
    uint32_t* sA1 = sA0 + NTILE * SW2;       // [64][SW2] buffer 1
    uint32_t sW_b  = smem_u32(sW);
    uint32_t sA0_b = smem_u32(sA0);
    uint32_t sA1_b = smem_u32(sA1);

    int t   = threadIdx.x;                   // 0..255
    int lid = t & 31;
    int wid = t >> 5;                        // 0..7
    int m0  = (wid & 1) * 32;                // 2 M groups
    int n0  = (wid >> 1) * 24;               // 4 N groups
    int g   = lid >> 2;                      // groupID 0..7
    int tig = lid & 3;                       // thread-in-group 0..3

    const char* ah_bytes = reinterpret_cast<const char*>(g_ah);
    const char* wh_bytes = reinterpret_cast<const char*>(g_wh);
    int stride = gridDim.x;

    // A-tile fill: 64 rows x 12 16B-chunks (row = 192B of data, pitch 208B)
    auto fill_A = [&](int tile, uint32_t buf_b) {
        int row0 = tile * NTILE;
        for (int i = t; i < NTILE * 12; i += 256) {
            int r = i / 12, c8 = i % 12;
            int gr = row0 + r;
            const char* src = ah_bytes + (size_t)gr * (D * 2) + c8 * 16;
            uint32_t dst = buf_b + (uint32_t)(r * (SW2 * 4) + c8 * 16);
            int sz = (gr < N) ? 16 : 0;
            asm volatile("cp.async.cg.shared.global [%0], [%1], 16, %2;"
                         :: "r"(dst), "l"(src), "r"(sz));
        }
    };

    // W fill (once per CTA): 96 rows x 12 chunks
    for (int i = t; i < D * 12; i += 256) {
        int r = i / 12, c8 = i % 12;
        const char* src = wh_bytes + (size_t)r * (D * 2) + c8 * 16;
        uint32_t dst = sW_b + (uint32_t)(r * (SW2 * 4) + c8 * 16);
        asm volatile("cp.async.cg.shared.global [%0], [%1], 16;"
                     :: "r"(dst), "l"(src));
    }
    int tile0 = blockIdx.x;
    if (tile0 < ntiles) fill_A(tile0, sA0_b);
    asm volatile("cp.async.commit_group;");

    int pipe = 0;
    for (int tile = tile0; tile < ntiles; tile += stride) {
        uint32_t* sA = pipe ? sA1 : sA0;

        asm volatile("cp.async.wait_group 0;");
        __syncthreads();

        int next = tile + stride;
        if (next < ntiles) fill_A(next, pipe ? sA0_b : sA1_b);
        asm volatile("cp.async.commit_group;");

        int row0 = tile * NTILE;

        float c[2][3][4];
#pragma unroll
        for (int mt = 0; mt < 2; mt++)
#pragma unroll
            for (int nt = 0; nt < 3; nt++)
#pragma unroll
                for (int q = 0; q < 4; q++) c[mt][nt][q] = 0.f;

#pragma unroll
        for (int ks = 0; ks < 6; ks++) {
            int kw = ks * 8;                 // k offset in 32-bit words

            uint32_t a[2][4];
#pragma unroll
            for (int mt = 0; mt < 2; mt++) {
                const uint32_t* base = sA + (m0 + mt * 16 + g) * SW2 + kw + tig;
                a[mt][0] = base[0];          // (row g,   k tig*2..+1)
                a[mt][1] = base[8 * SW2];    // (row g+8)
                a[mt][2] = base[4];          // (row g,   k +8)
                a[mt][3] = base[8 * SW2 + 4];
            }
            uint32_t bfr[3][2];
#pragma unroll
            for (int nt = 0; nt < 3; nt++) {
                const uint32_t* base = sW + (n0 + nt * 8 + g) * SW2 + kw + tig;
                bfr[nt][0] = base[0];        // (k tig*2..+1, n g)
                bfr[nt][1] = base[4];        // (k +8)
            }

#pragma unroll
            for (int mt = 0; mt < 2; mt++)
#pragma unroll
                for (int nt = 0; nt < 3; nt++) {
                    asm volatile(
                        "mma.sync.aligned.m16n8k16.row.col.f32.f16.f16.f32 "
                        "{%0,%1,%2,%3}, {%4,%5,%6,%7}, {%8,%9}, {%0,%1,%2,%3};"
                        : "+f"(c[mt][nt][0]), "+f"(c[mt][nt][1]),
                          "+f"(c[mt][nt][2]), "+f"(c[mt][nt][3])
                        : "r"(a[mt][0]), "r"(a[mt][1]), "r"(a[mt][2]), "r"(a[mt][3]),
                          "r"(bfr[nt][0]), "r"(bfr[nt][1]));
                }
        }

        // epilogue: c0,c1 -> (row, 2*tig),(row, 2*tig+1); c2,c3 -> row+8
#pragma unroll
        for (int nt = 0; nt < 3; nt++) {
            int col = n0 + nt * 8 + 2 * tig;
            float b0 = __ldg(bias + col);
            float b1 = __ldg(bias + col + 1);
#pragma unroll
            for (int mt = 0; mt < 2; mt++) {
                int r_lo = row0 + m0 + mt * 16 + g;
                if (r_lo < N) {
                    float2 v = make_float2(c[mt][nt][0] + b0, c[mt][nt][1] + b1);
                    *reinterpret_cast<float2*>(out + (size_t)r_lo * D + col) = v;
                }
                int r_hi = r_lo + 8;
                if (r_hi < N) {
                    float2 v = make_float2(c[mt][nt][2] + b0, c[mt][nt][3] + b1);
                    *reinterpret_cast<float2*>(out + (size_t)r_hi * D + col) = v;
                }
            }
        }

        __syncthreads();
        pipe ^= 1;
    }
}

// ---------------------------------------------------------------------------
// Launch. Inputs: x[N*D] f32, edge_index[2*E] i32, edge_weight[E] f32,
//                 pagerank[N] f32, W[D*D] f32, b[D] f32. Output f32 [N,D].
// ---------------------------------------------------------------------------
extern "C" void kernel_launch(void* const* d_in, const int* in_sizes, int n_in,
                              void* d_out, int out_size) {
    const float* x  = (const float*)d_in[0];
    const int*   ei = (const int*)  d_in[1];
    const float* ew = (const float*)d_in[2];
    const float* pr = (const float*)d_in[3];
    const float* Wm = (const float*)d_in[4];
    const float* b  = (const float*)d_in[5];
    float* out = (float*)d_out;

    int N = in_sizes[0] / D;
    int E = in_sizes[1] / 2;

    const int gemm_smem = (D * SW2 + 2 * NTILE * SW2) * (int)sizeof(uint32_t);
    cudaFuncSetAttribute(gemm_h_kernel,
                         cudaFuncAttributeMaxDynamicSharedMemorySize, gemm_smem);

    wconv_kernel<<<(D * D + 255) / 256, 256>>>(Wm);

    int nthread = (E + EPT - 1) / EPT;
    bucket_kernel<<<(nthread + 255) / 256, 256>>>(ei, ew, pr, E);

    int agg_blocks = (N + 7) / 8;
    aggregate_kernel<<<agg_blocks, 256>>>(x, N, agg_blocks * 8);

    int ntiles = (N + NTILE - 1) / NTILE;
    int grid = 444;                       // 3 x 148 SMs
    if (grid > ntiles) grid = ntiles;
    gemm_h_kernel<<<grid, 256, gemm_smem>>>(b, out, N, ntiles);
}

// round 17
// speedup vs baseline: 1.4394x; 1.4394x over previous
#include <cuda_runtime.h>
#include <cuda_fp16.h>
#include <cstdint>

#define D 96
#define MAX_N 50000
#define MAXDEG 64
#define MAX_OVF 4096

// ---- scratch (static device globals; no allocation) -----------------------
__device__ __align__(16) uint16_t g_ah[MAX_N * D];   // fp16 aggr + x
__device__ __align__(16) uint16_t g_wh[D * D];       // fp16 W
__device__ int      g_cnt[MAX_N];               // per-node cursor / degree
__device__ int2     g_pack[MAX_N * MAXDEG];     // (src, bitcast(w)) buckets
__device__ int      g_ovfcnt;
__device__ int4     g_ovf[MAX_OVF];             // (src, dst, bitcast(w), pad)

__device__ __forceinline__ uint32_t smem_u32(const void* p) {
    uint32_t a;
    asm("{ .reg .u64 t; cvta.to.shared.u64 t, %1; cvt.u32.u64 %0, t; }"
        : "=r"(a) : "l"(p));
    return a;
}

// ---------------------------------------------------------------------------
// K1: zero cursors + overflow counter; convert W to fp16.
// (Cheap dedicated kernel. NEVER funnel cleanup through one global atomic:
//  the R16 per-warp ticket cost ~25us of serialized single-address atomics.)
// ---------------------------------------------------------------------------
__global__ void zero_wconv_kernel(const float* __restrict__ Wm, int N) {
    int i = blockIdx.x * blockDim.x + threadIdx.x;
    if (i < N) g_cnt[i] = 0;
    if (i == 0) g_ovfcnt = 0;
    if (i < D * D)
        g_wh[i] = __half_as_ushort(__float2half_rn(__ldg(Wm + i)));
}

// ---------------------------------------------------------------------------
// K2: bucket edges. EPT=4, low regs, high occupancy (atomic-latency bound).
// ---------------------------------------------------------------------------
#define EPT 4
__global__ void bucket_kernel(const int* __restrict__ ei,
                              const float* __restrict__ ew,
                              const float* __restrict__ pr,
                              int E) {
    int base = (blockIdx.x * blockDim.x + threadIdx.x) * EPT;
    int src[EPT], dst[EPT];
    float w[EPT];
#pragma unroll
    for (int u = 0; u < EPT; u++) {
        int e = base + u;
        if (e < E) { src[u] = __ldg(ei + e); dst[u] = __ldg(ei + E + e); w[u] = __ldg(ew + e); }
    }
#pragma unroll
    for (int u = 0; u < EPT; u++) {
        int e = base + u;
        if (e < E) w[u] *= __ldg(pr + src[u]);
    }
#pragma unroll
    for (int u = 0; u < EPT; u++) {
        int e = base + u;
        if (e < E) {
            int pos = atomicAdd(&g_cnt[dst[u]], 1);
            if (pos < MAXDEG) {
                g_pack[dst[u] * MAXDEG + pos] = make_int2(src[u], __float_as_int(w[u]));
            } else {
                int o = atomicAdd(&g_ovfcnt, 1);
                if (o < MAX_OVF)
                    g_ovf[o] = make_int4(src[u], dst[u], __float_as_int(w[u]), 0);
            }
        }
    }
}

// ---------------------------------------------------------------------------
// K3: per-node aggregation (R8 form). One warp per node; residual +x folded;
// smem-staged pack list; unroll-4 gathers (12 loads in flight); fp32
// accumulate; fp16 output (coalesced 64B half-stores).
// ---------------------------------------------------------------------------
__global__ void aggregate_kernel(const float* __restrict__ x, int N) {
    __shared__ int2 s_pack[8][MAXDEG];

    int wid  = threadIdx.x >> 5;
    int l    = threadIdx.x & 31;
    int node = blockIdx.x * 8 + wid;
    if (node >= N) return;

    int cnt = g_cnt[node];
    if (cnt > MAXDEG) cnt = MAXDEG;

    const int2* bucket = g_pack + (size_t)node * MAXDEG;
    for (int k = l; k < cnt; k += 32)
        s_pack[wid][k] = __ldg(bucket + k);
    __syncwarp();

    const float* xr0 = x + (size_t)node * D;
    float a0 = __ldg(xr0 + l);
    float a1 = __ldg(xr0 + 32 + l);
    float a2 = __ldg(xr0 + 64 + l);

    int j = 0;
    for (; j + 4 <= cnt; j += 4) {
        int   s[4]; float w[4];
#pragma unroll
        for (int u = 0; u < 4; u++) {
            int2 p = s_pack[wid][j + u];
            s[u] = p.x; w[u] = __int_as_float(p.y);
        }
        float b0[4], b1[4], b2[4];
#pragma unroll
        for (int u = 0; u < 4; u++) {
            const float* xr = x + (size_t)s[u] * D;
            b0[u] = __ldg(xr + l);
            b1[u] = __ldg(xr + 32 + l);
            b2[u] = __ldg(xr + 64 + l);
        }
#pragma unroll
        for (int u = 0; u < 4; u++) {
            a0 += w[u] * b0[u];
            a1 += w[u] * b1[u];
            a2 += w[u] * b2[u];
        }
    }
    for (; j < cnt; j++) {
        int2 p = s_pack[wid][j];
        float w = __int_as_float(p.y);
        const float* xr = x + (size_t)p.x * D;
        a0 += w * __ldg(xr + l);
        a1 += w * __ldg(xr + 32 + l);
        a2 += w * __ldg(xr + 64 + l);
    }

    int ovf = g_ovfcnt;
    if (ovf > 0) {
        if (ovf > MAX_OVF) ovf = MAX_OVF;
        for (int i = 0; i < ovf; i++) {
            int4 p = g_ovf[i];
            if (p.y == node) {
                float w = __int_as_float(p.z);
                const float* xr = x + (size_t)p.x * D;
                a0 += w * __ldg(xr + l);
                a1 += w * __ldg(xr + 32 + l);
                a2 += w * __ldg(xr + 64 + l);
            }
        }
    }

    uint16_t* o = g_ah + (size_t)node * D;
    o[l]      = __half_as_ushort(__float2half_rn(a0));
    o[32 + l] = __half_as_ushort(__float2half_rn(a1));
    o[64 + l] = __half_as_ushort(__float2half_rn(a2));
}

// ---------------------------------------------------------------------------
// K4: fp16 mma.sync GEMM (m16n8k16) — grid-strided, double-buffered.
// (Measured 13.6us in R16.) Each CTA loads W once, loops 64-node tiles with
// a 2-deep cp.async A pipeline. 8 warps = 2M x 4N groups; warp tile 2m16x3n8;
// 6 K-steps of 16. smem pitch 52 words -> conflict-free fragment LDS.
// smem = 46.6KB -> 3 CTAs/SM.
// ---------------------------------------------------------------------------
#define SW2 52        // 32-bit words per smem row (104 halves)
#define NTILE 64
__global__ __launch_bounds__(256, 3)
void gemm_h_kernel(const float* __restrict__ bias,
                   float* __restrict__ out,
                   int N, int ntiles) {
    extern __shared__ uint32_t smem[];
    uint32_t* sW  = smem;                    // [96][SW2]
    uint32_t* sA0 = smem + D * SW2;          // [64][SW2] buffer 0
    uint32_t* sA1 = sA0 + NTILE * SW2;       // [64][SW2] buffer 1
    uint32_t sW_b  = smem_u32(sW);
    uint32_t sA0_b = smem_u32(sA0);
    uint32_t sA1_b = smem_u32(sA1);

    int t   = threadIdx.x;                   // 0..255
    int lid = t & 31;
    int wid = t >> 5;                        // 0..7
    int m0  = (wid & 1) * 32;                // 2 M groups
    int n0  = (wid >> 1) * 24;               // 4 N groups
    int g   = lid >> 2;                      // groupID 0..7
    int tig = lid & 3;                       // thread-in-group 0..3

    const char* ah_bytes = reinterpret_cast<const char*>(g_ah);
    const char* wh_bytes = reinterpret_cast<const char*>(g_wh);
    int stride = gridDim.x;

    auto fill_A = [&](int tile, uint32_t buf_b) {
        int row0 = tile * NTILE;
        for (int i = t; i < NTILE * 12; i += 256) {
            int r = i / 12, c8 = i % 12;
            int gr = row0 + r;
            const char* src = ah_bytes + (size_t)gr * (D * 2) + c8 * 16;
            uint32_t dst = buf_b + (uint32_t)(r * (SW2 * 4) + c8 * 16);
            int sz = (gr < N) ? 16 : 0;
            asm volatile("cp.async.cg.shared.global [%0], [%1], 16, %2;"
                         :: "r"(dst), "l"(src), "r"(sz));
        }
    };

    for (int i = t; i < D * 12; i += 256) {
        int r = i / 12, c8 = i % 12;
        const char* src = wh_bytes + (size_t)r * (D * 2) + c8 * 16;
        uint32_t dst = sW_b + (uint32_t)(r * (SW2 * 4) + c8 * 16);
        asm volatile("cp.async.cg.shared.global [%0], [%1], 16;"
                     :: "r"(dst), "l"(src));
    }
    int tile0 = blockIdx.x;
    if (tile0 < ntiles) fill_A(tile0, sA0_b);
    asm volatile("cp.async.commit_group;");

    int pipe = 0;
    for (int tile = tile0; tile < ntiles; tile += stride) {
        uint32_t* sA = pipe ? sA1 : sA0;

        asm volatile("cp.async.wait_group 0;");
        __syncthreads();

        int next = tile + stride;
        if (next < ntiles) fill_A(next, pipe ? sA0_b : sA1_b);
        asm volatile("cp.async.commit_group;");

        int row0 = tile * NTILE;

        float c[2][3][4];
#pragma unroll
        for (int mt = 0; mt < 2; mt++)
#pragma unroll
            for (int nt = 0; nt < 3; nt++)
#pragma unroll
                for (int q = 0; q < 4; q++) c[mt][nt][q] = 0.f;

#pragma unroll
        for (int ks = 0; ks < 6; ks++) {
            int kw = ks * 8;

            uint32_t a[2][4];
#pragma unroll
            for (int mt = 0; mt < 2; mt++) {
                const uint32_t* base = sA + (m0 + mt * 16 + g) * SW2 + kw + tig;
                a[mt][0] = base[0];
                a[mt][1] = base[8 * SW2];
                a[mt][2] = base[4];
                a[mt][3] = base[8 * SW2 + 4];
            }
            uint32_t bfr[3][2];
#pragma unroll
            for (int nt = 0; nt < 3; nt++) {
                const uint32_t* base = sW + (n0 + nt * 8 + g) * SW2 + kw + tig;
                bfr[nt][0] = base[0];
                bfr[nt][1] = base[4];
            }

#pragma unroll
            for (int mt = 0; mt < 2; mt++)
#pragma unroll
                for (int nt = 0; nt < 3; nt++) {
                    asm volatile(
                        "mma.sync.aligned.m16n8k16.row.col.f32.f16.f16.f32 "
                        "{%0,%1,%2,%3}, {%4,%5,%6,%7}, {%8,%9}, {%0,%1,%2,%3};"
                        : "+f"(c[mt][nt][0]), "+f"(c[mt][nt][1]),
                          "+f"(c[mt][nt][2]), "+f"(c[mt][nt][3])
                        : "r"(a[mt][0]), "r"(a[mt][1]), "r"(a[mt][2]), "r"(a[mt][3]),
                          "r"(bfr[nt][0]), "r"(bfr[nt][1]));
                }
        }

#pragma unroll
        for (int nt = 0; nt < 3; nt++) {
            int col = n0 + nt * 8 + 2 * tig;
            float b0 = __ldg(bias + col);
            float b1 = __ldg(bias + col + 1);
#pragma unroll
            for (int mt = 0; mt < 2; mt++) {
                int r_lo = row0 + m0 + mt * 16 + g;
                if (r_lo < N) {
                    float2 v = make_float2(c[mt][nt][0] + b0, c[mt][nt][1] + b1);
                    *reinterpret_cast<float2*>(out + (size_t)r_lo * D + col) = v;
                }
                int r_hi = r_lo + 8;
                if (r_hi < N) {
                    float2 v = make_float2(c[mt][nt][2] + b0, c[mt][nt][3] + b1);
                    *reinterpret_cast<float2*>(out + (size_t)r_hi * D + col) = v;
                }
            }
        }

        __syncthreads();
        pipe ^= 1;
    }
}

// ---------------------------------------------------------------------------
// Launch. Inputs: x[N*D] f32, edge_index[2*E] i32, edge_weight[E] f32,
//                 pagerank[N] f32, W[D*D] f32, b[D] f32. Output f32 [N,D].
// ---------------------------------------------------------------------------
extern "C" void kernel_launch(void* const* d_in, const int* in_sizes, int n_in,
                              void* d_out, int out_size) {
    const float* x  = (const float*)d_in[0];
    const int*   ei = (const int*)  d_in[1];
    const float* ew = (const float*)d_in[2];
    const float* pr = (const float*)d_in[3];
    const float* Wm = (const float*)d_in[4];
    const float* b  = (const float*)d_in[5];
    float* out = (float*)d_out;

    int N = in_sizes[0] / D;
    int E = in_sizes[1] / 2;

    const int gemm_smem = (D * SW2 + 2 * NTILE * SW2) * (int)sizeof(uint32_t);
    cudaFuncSetAttribute(gemm_h_kernel,
                         cudaFuncAttributeMaxDynamicSharedMemorySize, gemm_smem);

    zero_wconv_kernel<<<(N + 255) / 256, 256>>>(Wm, N);

    int nthread = (E + EPT - 1) / EPT;
    bucket_kernel<<<(nthread + 255) / 256, 256>>>(ei, ew, pr, E);

    aggregate_kernel<<<(N + 7) / 8, 256>>>(x, N);

    int ntiles = (N + NTILE - 1) / NTILE;
    int grid = 444;                       // 3 x 148 SMs
    if (grid > ntiles) grid = ntiles;
    gemm_h_kernel<<<grid, 256, gemm_smem>>>(b, out, N, ntiles);
}